// round 7
// baseline (speedup 1.0000x reference)
#include <cuda_runtime.h>
#include <cstdint>

#define NN 50000
#define NE 800000
#define D  128
#define DE 16
#define DM 128

// ---------------------------------------------------------------------------
// Global scratch
// ---------------------------------------------------------------------------
__device__ float g_agg[NN * DM];
// bf16 fragment-packed weights: uint2{b0,b1} per (K16, nb, lane)
//   b0 = bf16x2(W[k0+2t][n], W[k0+2t+1][n]), b1 = same at k0+8
__device__ __align__(16) uint2 g_w1b[18 * 16 * 32];   // We1, K 272->288
__device__ __align__(16) uint2 g_w2b[8 * 16 * 32];    // We2, K=128
__device__ __align__(16) uint2 g_wn1b[16 * 16 * 32];  // Wn1, K=256
__device__ __align__(16) uint2 g_wn2b[8 * 16 * 32];   // Wn2, K=128

// ---------------------------------------------------------------------------
// helpers
// ---------------------------------------------------------------------------
__device__ __forceinline__ float siluf(float x) { return x / (1.0f + __expf(-x)); }
__device__ __forceinline__ float sigmoidf_(float x) { return 1.0f / (1.0f + __expf(-x)); }

__device__ __forceinline__ uint32_t bf2(float lo, float hi) {
    uint32_t r;
    asm("cvt.rn.bf16x2.f32 %0, %1, %2;" : "=r"(r) : "f"(hi), "f"(lo));
    return r;
}
__device__ __forceinline__ void mma_bf16(float c[4], const uint32_t a[4],
                                         uint32_t b0, uint32_t b1) {
    asm volatile("mma.sync.aligned.m16n8k16.row.col.f32.bf16.bf16.f32 "
        "{%0,%1,%2,%3}, {%4,%5,%6,%7}, {%8,%9}, {%0,%1,%2,%3};"
        : "+f"(c[0]), "+f"(c[1]), "+f"(c[2]), "+f"(c[3])
        : "r"(a[0]), "r"(a[1]), "r"(a[2]), "r"(a[3]), "r"(b0), "r"(b1));
}
__device__ __forceinline__ void red_add_v2(float* p, float a, float b) {
    asm volatile("red.global.add.v2.f32 [%0], {%1, %2};"
                 :: "l"(p), "f"(a), "f"(b) : "memory");
}

// ===========================================================================
// EDGE KERNEL — weight-resident, 1 CTA/SM, grid-stride over 128-edge tiles
// ===========================================================================
// SMEM layout (bytes):
#define E_W1S    0                       // 73728  (18 K16 blocks)
#define E_W2S    73728                   // 32768  (8 K16 blocks)
#define E_A0     106496                  // 10240  (128 rows x 80B bf16)
#define E_A1     116736                  // 10240
#define E_HB     126976                  // 34816  (128 rows x 272B bf16)
#define E_MS     161792
#define E_STARTS (E_MS)
#define E_ENDS   (E_MS + 512)
#define E_BE1S   (E_MS + 1024)
#define E_BE2S   (E_MS + 1536)
#define E_WIS    (E_MS + 2048)
#define E_GATES  (E_MS + 2560)
#define E_GPART  (E_MS + 3072)           // 128*2 floats
#define E_SMEM_BYTES (E_MS + 4096)       // 165888

__device__ __forceinline__ void gather_A(int c, int tid, int e0,
                                         const int* starts, const int* ends,
                                         const float* __restrict__ nf,
                                         const float* __restrict__ ef,
                                         float4 va[4]) {
#pragma unroll
    for (int it = 0; it < 4; it++) {
        int seg = tid + it * 256;
        int e = seg >> 3, s8 = seg & 7;
        int k0 = c * 32;
        float4 v;
        if (c < 4)       v = *(const float4*)(nf + (size_t)starts[e] * D + k0 + s8 * 4);
        else if (c < 8)  v = *(const float4*)(nf + (size_t)ends[e] * D + (k0 - 128) + s8 * 4);
        else {
            if (s8 < 4)  v = *(const float4*)(ef + (size_t)(e0 + e) * DE + s8 * 4);
            else         v = make_float4(0.f, 0.f, 0.f, 0.f);
        }
        va[it] = v;
    }
}
__device__ __forceinline__ void store_A(char* Ab, int tid, const float4 va[4]) {
#pragma unroll
    for (int it = 0; it < 4; it++) {
        int seg = tid + it * 256;
        int e = seg >> 3, s8 = seg & 7;
        uint2 u = make_uint2(bf2(va[it].x, va[it].y), bf2(va[it].z, va[it].w));
        *(uint2*)(Ab + e * 80 + s8 * 8) = u;
    }
}

__global__ void __launch_bounds__(256, 1)
edge_kernel(const float* __restrict__ nf, const int* __restrict__ ei,
            const float* __restrict__ ef,
            const float* __restrict__ be1, const float* __restrict__ be2,
            const float* __restrict__ Wi, const float* __restrict__ bi,
            float* __restrict__ agg) {
    extern __shared__ char smem[];
    char*  hbuf   = smem + E_HB;
    int*   starts = (int*)(smem + E_STARTS);
    int*   ends   = (int*)(smem + E_ENDS);
    float* be1s   = (float*)(smem + E_BE1S);
    float* be2s   = (float*)(smem + E_BE2S);
    float* wis    = (float*)(smem + E_WIS);
    float* gates  = (float*)(smem + E_GATES);
    float* gpart  = (float*)(smem + E_GPART);

    const int tid  = threadIdx.x;
    const int lane = tid & 31;
    const int wid  = tid >> 5;
    const int wr   = wid & 3;
    const int wc   = wid >> 2;
    const int g    = lane >> 2;
    const int t    = lane & 3;
    const float bi0 = __ldg(bi);

    // ---- load weights to smem ONCE per block ----
    {
        const float4* s1 = (const float4*)g_w1b;
        float4* d1 = (float4*)(smem + E_W1S);
#pragma unroll
        for (int it = 0; it < 18; it++) d1[tid + it * 256] = s1[tid + it * 256];
        const float4* s2 = (const float4*)g_w2b;
        float4* d2 = (float4*)(smem + E_W2S);
#pragma unroll
        for (int it = 0; it < 8; it++) d2[tid + it * 256] = s2[tid + it * 256];
    }
    if (tid < 128) {
        be1s[tid] = be1[tid];
        be2s[tid] = be2[tid];
        wis[tid]  = Wi[tid];
    }

    for (int tile = blockIdx.x; tile < NE / 128; tile += gridDim.x) {
        const int e0 = tile * 128;
        __syncthreads();   // prev tile fully done (and weight load on iter 0)
        if (tid < 128) {
            starts[tid] = ei[e0 + tid];
            ends[tid]   = ei[NE + e0 + tid];
        }
        __syncthreads();

        float acc[2][8][4];
#pragma unroll
        for (int rg = 0; rg < 2; rg++)
#pragma unroll
            for (int nb = 0; nb < 8; nb++)
#pragma unroll
                for (int i = 0; i < 4; i++) acc[rg][nb][i] = 0.0f;

        // ---------------- GEMM1: K=288, 9 chunks, A double-buffered ---------
        float4 va[4];
        gather_A(0, tid, e0, starts, ends, nf, ef, va);
        store_A(smem + E_A0, tid, va);
        __syncthreads();
        for (int c = 0; c < 9; c++) {
            if (c < 8) gather_A(c + 1, tid, e0, starts, ends, nf, ef, va);
            const char* Ab = smem + ((c & 1) ? E_A1 : E_A0);
            const uint2* Bs = (const uint2*)(smem + E_W1S + c * 8192);
#pragma unroll
            for (int kcl = 0; kcl < 2; kcl++) {
                uint32_t a[2][4];
#pragma unroll
                for (int rg = 0; rg < 2; rg++) {
                    const char* p = Ab + (wr * 32 + rg * 16 + g) * 80 + kcl * 32 + t * 4;
                    a[rg][0] = *(const uint32_t*)p;
                    a[rg][1] = *(const uint32_t*)(p + 8 * 80);
                    a[rg][2] = *(const uint32_t*)(p + 16);
                    a[rg][3] = *(const uint32_t*)(p + 8 * 80 + 16);
                }
#pragma unroll
                for (int nb = 0; nb < 8; nb++) {
                    uint2 b = Bs[(kcl * 16 + wc * 8 + nb) * 32 + lane];
                    mma_bf16(acc[0][nb], a[0], b.x, b.y);
                    mma_bf16(acc[1][nb], a[1], b.x, b.y);
                }
            }
            __syncthreads();
            if (c < 8) {
                store_A(smem + (((c + 1) & 1) ? E_A1 : E_A0), tid, va);
                __syncthreads();
            }
        }

        // ---------------- Epilogue 1: h = silu(D1+be1) -> hbuf (bf16) -------
#pragma unroll
        for (int rg = 0; rg < 2; rg++) {
            int row0 = wr * 32 + rg * 16 + g;
#pragma unroll
            for (int nb = 0; nb < 8; nb++) {
                int col = wc * 64 + nb * 8 + 2 * t;
                float b0 = be1s[col], b1 = be1s[col + 1];
                uint32_t h0 = bf2(siluf(acc[rg][nb][0] + b0), siluf(acc[rg][nb][1] + b1));
                uint32_t h1 = bf2(siluf(acc[rg][nb][2] + b0), siluf(acc[rg][nb][3] + b1));
                *(uint32_t*)(hbuf + row0 * 272 + col * 2) = h0;
                *(uint32_t*)(hbuf + (row0 + 8) * 272 + col * 2) = h1;
                acc[rg][nb][0] = 0.f; acc[rg][nb][1] = 0.f;
                acc[rg][nb][2] = 0.f; acc[rg][nb][3] = 0.f;
            }
        }
        __syncthreads();

        // ---------------- GEMM2: K=128, sync-free, B = W2S resident ---------
        {
            const uint2* B2 = (const uint2*)(smem + E_W2S);
#pragma unroll
            for (int K16 = 0; K16 < 8; K16++) {
                uint32_t a[2][4];
#pragma unroll
                for (int rg = 0; rg < 2; rg++) {
                    const char* p = hbuf + (wr * 32 + rg * 16 + g) * 272 + K16 * 32 + t * 4;
                    a[rg][0] = *(const uint32_t*)p;
                    a[rg][1] = *(const uint32_t*)(p + 8 * 272);
                    a[rg][2] = *(const uint32_t*)(p + 16);
                    a[rg][3] = *(const uint32_t*)(p + 8 * 272 + 16);
                }
#pragma unroll
                for (int nb = 0; nb < 8; nb++) {
                    uint2 b = B2[(K16 * 16 + wc * 8 + nb) * 32 + lane];
                    mma_bf16(acc[0][nb], a[0], b.x, b.y);
                    mma_bf16(acc[1][nb], a[1], b.x, b.y);
                }
            }
        }

        // ---------------- Epilogue 2 in registers: m = D2 + be2 -------------
#pragma unroll
        for (int rg = 0; rg < 2; rg++)
#pragma unroll
            for (int nb = 0; nb < 8; nb++) {
                int col = wc * 64 + nb * 8 + 2 * t;
                float b0 = be2s[col], b1 = be2s[col + 1];
                acc[rg][nb][0] += b0; acc[rg][nb][1] += b1;
                acc[rg][nb][2] += b0; acc[rg][nb][3] += b1;
            }

        // gate partials: dot(m[row, wc-half], Wi) via quad shfl reduction
        {
            float p[2][2] = {{0.f, 0.f}, {0.f, 0.f}};
#pragma unroll
            for (int rg = 0; rg < 2; rg++)
#pragma unroll
                for (int nb = 0; nb < 8; nb++) {
                    int col = wc * 64 + nb * 8 + 2 * t;
                    float w0 = wis[col], w1 = wis[col + 1];
                    p[rg][0] += acc[rg][nb][0] * w0 + acc[rg][nb][1] * w1;
                    p[rg][1] += acc[rg][nb][2] * w0 + acc[rg][nb][3] * w1;
                }
#pragma unroll
            for (int rg = 0; rg < 2; rg++)
#pragma unroll
                for (int h = 0; h < 2; h++) {
                    float v = p[rg][h];
                    v += __shfl_xor_sync(0xffffffffu, v, 1);
                    v += __shfl_xor_sync(0xffffffffu, v, 2);
                    p[rg][h] = v;
                }
            if (t == 0) {
#pragma unroll
                for (int rg = 0; rg < 2; rg++)
#pragma unroll
                    for (int h = 0; h < 2; h++) {
                        int row = wr * 32 + rg * 16 + g + 8 * h;
                        gpart[row * 2 + wc] = p[rg][h];
                    }
            }
        }
        __syncthreads();
        if (tid < 128)
            gates[tid] = sigmoidf_(gpart[2 * tid] + gpart[2 * tid + 1] + bi0);
        __syncthreads();

        // gated scatter from registers (red.v2)
#pragma unroll
        for (int rg = 0; rg < 2; rg++)
#pragma unroll
            for (int h = 0; h < 2; h++) {
                int row = wr * 32 + rg * 16 + g + 8 * h;
                float gt = gates[row];
                float* dst = agg + (size_t)starts[row] * DM + wc * 64 + 2 * t;
#pragma unroll
                for (int nb = 0; nb < 8; nb++) {
                    float m0 = (h ? acc[rg][nb][2] : acc[rg][nb][0]) * gt;
                    float m1 = (h ? acc[rg][nb][3] : acc[rg][nb][1]) * gt;
                    red_add_v2(dst + nb * 8, m0, m1);
                }
            }
    }
}

// ===========================================================================
// NODE KERNEL — bf16 mma, fp32 residual
// ===========================================================================
#define N_A0  0
#define N_A1  10240
#define N_B0  20480
#define N_B1  28672
#define N_HB  36864          // 34816 -> 71680
#define N_BN1 71680
#define N_BN2 72192
#define N_SMEM_BYTES 72704

__global__ void __launch_bounds__(256, 2)
node_kernel(const float* __restrict__ nf, const float* __restrict__ agg,
            const float* __restrict__ bn1, const float* __restrict__ bn2,
            float* __restrict__ out) {
    extern __shared__ char smem[];
    char*  hbuf  = smem + N_HB;
    float* bn1s  = (float*)(smem + N_BN1);
    float* bn2s  = (float*)(smem + N_BN2);

    const int tid  = threadIdx.x;
    const int lane = tid & 31;
    const int wid  = tid >> 5;
    const int wr   = wid & 3;
    const int wc   = wid >> 2;
    const int g    = lane >> 2;
    const int t    = lane & 3;
    const int n0   = blockIdx.x * 128;

    if (tid < 128) { bn1s[tid] = bn1[tid]; bn2s[tid] = bn2[tid]; }

    float acc[2][8][4];
#pragma unroll
    for (int rg = 0; rg < 2; rg++)
#pragma unroll
        for (int nb = 0; nb < 8; nb++)
#pragma unroll
            for (int i = 0; i < 4; i++) acc[rg][nb][i] = 0.0f;

    // ---------------- GEMM1: K=256, 8 chunks, double-buffered ---------------
    {
        float4 va[4], vb[2];
        const float4* w1 = (const float4*)g_wn1b;
        // prefetch chunk 0
#pragma unroll
        for (int it = 0; it < 4; it++) {
            int seg = tid + it * 256;
            int e = seg >> 3, s8 = seg & 7;
            int n = n0 + e; if (n >= NN) n = NN - 1;
            va[it] = *(const float4*)(nf + (size_t)n * D + s8 * 4);
        }
#pragma unroll
        for (int it = 0; it < 2; it++) vb[it] = w1[tid + it * 256];
        store_A(smem + N_A0, tid, va);
        {
            float4* dst = (float4*)(smem + N_B0);
#pragma unroll
            for (int it = 0; it < 2; it++) dst[tid + it * 256] = vb[it];
        }
        __syncthreads();

        for (int c = 0; c < 8; c++) {
            const int buf = c & 1;
            if (c < 7) {
                int cn = c + 1;
#pragma unroll
                for (int it = 0; it < 4; it++) {
                    int seg = tid + it * 256;
                    int e = seg >> 3, s8 = seg & 7;
                    int n = n0 + e; if (n >= NN) n = NN - 1;
                    const float* src = (cn < 4)
                        ? nf  + (size_t)n * D  + cn * 32 + s8 * 4
                        : agg + (size_t)n * DM + (cn - 4) * 32 + s8 * 4;
                    va[it] = *(const float4*)src;
                }
#pragma unroll
                for (int it = 0; it < 2; it++)
                    vb[it] = w1[cn * 512 + tid + it * 256];
            }
            const char* Ab = smem + (buf ? N_A1 : N_A0);
            const uint2* Bs = (const uint2*)(smem + (buf ? N_B1 : N_B0));
#pragma unroll
            for (int kcl = 0; kcl < 2; kcl++) {
                uint32_t a[2][4];
#pragma unroll
                for (int rg = 0; rg < 2; rg++) {
                    const char* p = Ab + (wr * 32 + rg * 16 + g) * 80 + kcl * 32 + t * 4;
                    a[rg][0] = *(const uint32_t*)p;
                    a[rg][1] = *(const uint32_t*)(p + 8 * 80);
                    a[rg][2] = *(const uint32_t*)(p + 16);
                    a[rg][3] = *(const uint32_t*)(p + 8 * 80 + 16);
                }
#pragma unroll
                for (int nb = 0; nb < 8; nb++) {
                    uint2 b = Bs[(kcl * 16 + wc * 8 + nb) * 32 + lane];
                    mma_bf16(acc[0][nb], a[0], b.x, b.y);
                    mma_bf16(acc[1][nb], a[1], b.x, b.y);
                }
            }
            __syncthreads();
            if (c < 7) {
                store_A(smem + (((c + 1) & 1) ? N_A1 : N_A0), tid, va);
                float4* dst = (float4*)(smem + (((c + 1) & 1) ? N_B1 : N_B0));
#pragma unroll
                for (int it = 0; it < 2; it++) dst[tid + it * 256] = vb[it];
                __syncthreads();
            }
        }
    }

    // ---- Epilogue 1: stage Wn2 (32KB) + h = silu(D1+bn1) -> hbuf (bf16) ----
    {
        const float4* src = (const float4*)g_wn2b;
        float4* dst = (float4*)(smem + N_A0);
#pragma unroll
        for (int it = 0; it < 8; it++) dst[tid + it * 256] = src[tid + it * 256];
    }
#pragma unroll
    for (int rg = 0; rg < 2; rg++) {
        int row0 = wr * 32 + rg * 16 + g;
#pragma unroll
        for (int nb = 0; nb < 8; nb++) {
            int col = wc * 64 + nb * 8 + 2 * t;
            float b0 = bn1s[col], b1 = bn1s[col + 1];
            uint32_t h0 = bf2(siluf(acc[rg][nb][0] + b0), siluf(acc[rg][nb][1] + b1));
            uint32_t h1 = bf2(siluf(acc[rg][nb][2] + b0), siluf(acc[rg][nb][3] + b1));
            *(uint32_t*)(hbuf + row0 * 272 + col * 2) = h0;
            *(uint32_t*)(hbuf + (row0 + 8) * 272 + col * 2) = h1;
            acc[rg][nb][0] = 0.f; acc[rg][nb][1] = 0.f;
            acc[rg][nb][2] = 0.f; acc[rg][nb][3] = 0.f;
        }
    }
    __syncthreads();

    // ---------------- GEMM2: K=128, sync-free ------------------------------
    {
        const uint2* B2 = (const uint2*)(smem + N_A0);
#pragma unroll
        for (int K16 = 0; K16 < 8; K16++) {
            uint32_t a[2][4];
#pragma unroll
            for (int rg = 0; rg < 2; rg++) {
                const char* p = hbuf + (wr * 32 + rg * 16 + g) * 272 + K16 * 32 + t * 4;
                a[rg][0] = *(const uint32_t*)p;
                a[rg][1] = *(const uint32_t*)(p + 8 * 272);
                a[rg][2] = *(const uint32_t*)(p + 16);
                a[rg][3] = *(const uint32_t*)(p + 8 * 272 + 16);
            }
#pragma unroll
            for (int nb = 0; nb < 8; nb++) {
                uint2 b = B2[(K16 * 16 + wc * 8 + nb) * 32 + lane];
                mma_bf16(acc[0][nb], a[0], b.x, b.y);
                mma_bf16(acc[1][nb], a[1], b.x, b.y);
            }
        }
    }

    // ---------------- Epilogue 2: out = nf + D2 + bn2 (fp32 residual) -------
#pragma unroll
    for (int rg = 0; rg < 2; rg++) {
        int r0 = wr * 32 + rg * 16 + g;
#pragma unroll
        for (int h = 0; h < 2; h++) {
            int n = n0 + r0 + 8 * h;
            if (n >= NN) continue;
#pragma unroll
            for (int nb = 0; nb < 8; nb++) {
                int col = wc * 64 + nb * 8 + 2 * t;
                float2 res = *(const float2*)(nf + (size_t)n * D + col);
                float a0 = (h ? acc[rg][nb][2] : acc[rg][nb][0]) + bn2s[col] + res.x;
                float a1 = (h ? acc[rg][nb][3] : acc[rg][nb][1]) + bn2s[col + 1] + res.y;
                *(float2*)(out + (size_t)n * D + col) = make_float2(a0, a1);
            }
        }
    }
}

// ---------------------------------------------------------------------------
// Weight prep: pack all 4 edge/node weights into bf16 fragment layout
// ---------------------------------------------------------------------------
__device__ __forceinline__ uint2 pack_frag(const float* W, int idx, int K, int Kpad_check) {
    int lane = idx & 31;
    int nbk = idx >> 5;
    int k0 = (nbk >> 4) * 16;
    int n = (nbk & 15) * 8 + (lane >> 2);
    int t2 = (lane & 3) * 2;
    float v00 = (k0 + t2     < K) ? W[(size_t)(k0 + t2) * 128 + n] : 0.0f;
    float v01 = (k0 + t2 + 1 < K) ? W[(size_t)(k0 + t2 + 1) * 128 + n] : 0.0f;
    float v10 = (k0 + t2 + 8 < K) ? W[(size_t)(k0 + t2 + 8) * 128 + n] : 0.0f;
    float v11 = (k0 + t2 + 9 < K) ? W[(size_t)(k0 + t2 + 9) * 128 + n] : 0.0f;
    return make_uint2(bf2(v00, v01), bf2(v10, v11));
}

__global__ void prep_kernel(const float* __restrict__ We1, const float* __restrict__ We2,
                            const float* __restrict__ Wn1, const float* __restrict__ Wn2) {
    int i = blockIdx.x * 256 + threadIdx.x;
    if (i < 9216) {
        g_w1b[i] = pack_frag(We1, i, 272, 288);
    } else if (i < 13312) {
        g_w2b[i - 9216] = pack_frag(We2, i - 9216, 128, 128);
    } else if (i < 21504) {
        g_wn1b[i - 13312] = pack_frag(Wn1, i - 13312, 256, 256);
    } else if (i < 25600) {
        g_wn2b[i - 21504] = pack_frag(Wn2, i - 21504, 128, 128);
    }
}

// ---------------------------------------------------------------------------
__global__ void idx_to_float_kernel(const int4* __restrict__ ei,
                                    float4* __restrict__ out) {
    int i = blockIdx.x * blockDim.x + threadIdx.x;
    if (i < (2 * NE) / 4) {
        int4 v = ei[i];
        out[i] = make_float4((float)v.x, (float)v.y, (float)v.z, (float)v.w);
    }
}

// ---------------------------------------------------------------------------
extern "C" void kernel_launch(void* const* d_in, const int* in_sizes, int n_in,
                              void* d_out, int out_size) {
    const float* nf  = (const float*)d_in[0];
    const int*   ei  = (const int*)d_in[1];
    const float* ef  = (const float*)d_in[2];
    const float* We1 = (const float*)d_in[3];
    const float* be1 = (const float*)d_in[4];
    const float* We2 = (const float*)d_in[5];
    const float* be2 = (const float*)d_in[6];
    const float* Wi  = (const float*)d_in[7];
    const float* bi  = (const float*)d_in[8];
    const float* Wn1 = (const float*)d_in[9];
    const float* bn1 = (const float*)d_in[10];
    const float* Wn2 = (const float*)d_in[11];
    const float* bn2 = (const float*)d_in[12];
    float* out = (float*)d_out;

    cudaFuncSetAttribute(edge_kernel, cudaFuncAttributeMaxDynamicSharedMemorySize, E_SMEM_BYTES);
    cudaFuncSetAttribute(node_kernel, cudaFuncAttributeMaxDynamicSharedMemorySize, N_SMEM_BYTES);

    void* aggp = nullptr;
    cudaGetSymbolAddress(&aggp, g_agg);
    cudaMemsetAsync(aggp, 0, (size_t)NN * DM * sizeof(float));

    prep_kernel<<<(25600 + 255) / 256, 256>>>(We1, We2, Wn1, Wn2);

    edge_kernel<<<444, 256, E_SMEM_BYTES>>>(nf, ei, ef, be1, be2, Wi, bi,
                                            (float*)aggp);
    node_kernel<<<(NN + 127) / 128, 256, N_SMEM_BYTES>>>(nf, (const float*)aggp,
                                                         bn1, bn2, out);

    idx_to_float_kernel<<<((2 * NE / 4) + 255) / 256, 256>>>(
        (const int4*)ei, (float4*)(out + (size_t)NN * D));
    cudaMemcpyAsync(out + (size_t)NN * D + 2ull * NE, d_in[2],
                    (size_t)NE * DE * sizeof(float), cudaMemcpyDeviceToDevice);
}

// round 8
// speedup vs baseline: 1.1750x; 1.1750x over previous
#include <cuda_runtime.h>
#include <cstdint>

#define NN 50000
#define NE 800000
#define D  128
#define DE 16
#define DM 128

// ---------------------------------------------------------------------------
// Global scratch
// ---------------------------------------------------------------------------
__device__ float g_agg[NN * DM];
__device__ int   g_hist[NN];
__device__ int   g_off[NN];
__device__ int   g_cnt[NN];
__device__ int   g_perm[NE];
// bf16 fragment-packed weights: uint2{b0,b1} per (K16, nb, lane)
__device__ __align__(16) uint2 g_w1b[18 * 16 * 32];   // We1, K 272->288
__device__ __align__(16) uint2 g_w2b[8 * 16 * 32];    // We2, K=128
__device__ __align__(16) uint2 g_wn1b[16 * 16 * 32];  // Wn1, K=256
__device__ __align__(16) uint2 g_wn2b[8 * 16 * 32];   // Wn2, K=128

// ---------------------------------------------------------------------------
// helpers
// ---------------------------------------------------------------------------
__device__ __forceinline__ float siluf(float x) { return x / (1.0f + __expf(-x)); }
__device__ __forceinline__ float sigmoidf_(float x) { return 1.0f / (1.0f + __expf(-x)); }

__device__ __forceinline__ uint32_t bf2(float lo, float hi) {
    uint32_t r;
    asm("cvt.rn.bf16x2.f32 %0, %1, %2;" : "=r"(r) : "f"(hi), "f"(lo));
    return r;
}
__device__ __forceinline__ void mma_bf16(float c[4], const uint32_t a[4],
                                         uint32_t b0, uint32_t b1) {
    asm volatile("mma.sync.aligned.m16n8k16.row.col.f32.bf16.bf16.f32 "
        "{%0,%1,%2,%3}, {%4,%5,%6,%7}, {%8,%9}, {%0,%1,%2,%3};"
        : "+f"(c[0]), "+f"(c[1]), "+f"(c[2]), "+f"(c[3])
        : "r"(a[0]), "r"(a[1]), "r"(a[2]), "r"(a[3]), "r"(b0), "r"(b1));
}

// ---------------------------------------------------------------------------
// Edge kernel SMEM layout (bytes) — R6 layout + eidx
//   mtile f32 [128][132] (=67584B) overlays hbuf/A/B in the late phase
// ---------------------------------------------------------------------------
#define E_HBUF   0            // 34816 (128 rows x 272B bf16)
#define E_A0     34816        // 10240 (128 rows x 80B bf16)
#define E_A1     45056
#define E_B0     55296        // 8192
#define E_B1     63488
#define E_MISC   71680
#define E_STARTS (E_MISC)
#define E_ENDS   (E_MISC + 512)
#define E_EIDX   (E_MISC + 1024)
#define E_BE1    (E_MISC + 1536)
#define E_BE2    (E_MISC + 2048)
#define E_WIS    (E_MISC + 2560)
#define E_GATES  (E_MISC + 3072)
#define E_SMEM_BYTES (E_MISC + 3584)

__device__ __forceinline__ void gather_A(int c, int tid,
                                         const int* starts, const int* ends,
                                         const int* eidx,
                                         const float* __restrict__ nf,
                                         const float* __restrict__ ef,
                                         float4 va[4]) {
#pragma unroll
    for (int it = 0; it < 4; it++) {
        int seg = tid + it * 256;
        int e = seg >> 3, s8 = seg & 7;
        int k0 = c * 32;
        float4 v;
        if (c < 4)       v = *(const float4*)(nf + (size_t)starts[e] * D + k0 + s8 * 4);
        else if (c < 8)  v = *(const float4*)(nf + (size_t)ends[e] * D + (k0 - 128) + s8 * 4);
        else {
            if (s8 < 4)  v = *(const float4*)(ef + (size_t)eidx[e] * DE + s8 * 4);
            else         v = make_float4(0.f, 0.f, 0.f, 0.f);
        }
        va[it] = v;
    }
}
__device__ __forceinline__ void store_A(char* Ab, int tid, const float4 va[4]) {
#pragma unroll
    for (int it = 0; it < 4; it++) {
        int seg = tid + it * 256;
        int e = seg >> 3, s8 = seg & 7;
        uint2 u = make_uint2(bf2(va[it].x, va[it].y), bf2(va[it].z, va[it].w));
        *(uint2*)(Ab + e * 80 + s8 * 8) = u;
    }
}

// ---------------------------------------------------------------------------
// Edge kernel: sorted tiles -> bf16 mma MLP -> gate -> SEGMENTED scatter
// ---------------------------------------------------------------------------
__global__ void __launch_bounds__(256, 2)
edge_kernel(const float* __restrict__ nf, const int* __restrict__ ei,
            const float* __restrict__ ef,
            const float* __restrict__ be1, const float* __restrict__ be2,
            const float* __restrict__ Wi, const float* __restrict__ bi,
            float* __restrict__ agg) {
    extern __shared__ char smem[];
    float* mtile  = (float*)smem;
    char*  hbuf   = smem + E_HBUF;
    int*   starts = (int*)(smem + E_STARTS);
    int*   ends   = (int*)(smem + E_ENDS);
    int*   eidx   = (int*)(smem + E_EIDX);
    float* be1s   = (float*)(smem + E_BE1);
    float* be2s   = (float*)(smem + E_BE2);
    float* wis    = (float*)(smem + E_WIS);
    float* gates  = (float*)(smem + E_GATES);

    const int tid  = threadIdx.x;
    const int lane = tid & 31;
    const int wid  = tid >> 5;
    const int wr   = wid & 3;
    const int wc   = wid >> 2;
    const int g    = lane >> 2;
    const int t    = lane & 3;
    const int e0   = blockIdx.x * 128;

    if (tid < 128) {
        int e = g_perm[e0 + tid];
        eidx[tid]   = e;
        starts[tid] = ei[e];
        ends[tid]   = ei[NE + e];
        be1s[tid]   = be1[tid];
        be2s[tid]   = be2[tid];
        wis[tid]    = Wi[tid];
    }
    __syncthreads();

    float acc[2][8][4];
#pragma unroll
    for (int rg = 0; rg < 2; rg++)
#pragma unroll
        for (int nb = 0; nb < 8; nb++)
#pragma unroll
            for (int i = 0; i < 4; i++) acc[rg][nb][i] = 0.0f;

    // ================= GEMM1: K=288 (9 chunks), A+B double-buffered =========
    {
        float4 va[4], vb[2];
        gather_A(0, tid, starts, ends, eidx, nf, ef, va);
        const float4* w1 = (const float4*)g_w1b;
#pragma unroll
        for (int it = 0; it < 2; it++) vb[it] = w1[tid + it * 256];
        store_A(smem + E_A0, tid, va);
        {
            float4* dst = (float4*)(smem + E_B0);
#pragma unroll
            for (int it = 0; it < 2; it++) dst[tid + it * 256] = vb[it];
        }
        __syncthreads();

        for (int c = 0; c < 9; c++) {
            const int buf = c & 1;
            if (c < 8) {
                gather_A(c + 1, tid, starts, ends, eidx, nf, ef, va);
#pragma unroll
                for (int it = 0; it < 2; it++)
                    vb[it] = w1[(c + 1) * 512 + tid + it * 256];
            }
            const char* Ab = smem + (buf ? E_A1 : E_A0);
            const uint2* Bs = (const uint2*)(smem + (buf ? E_B1 : E_B0));
#pragma unroll
            for (int kcl = 0; kcl < 2; kcl++) {
                uint32_t a[2][4];
#pragma unroll
                for (int rg = 0; rg < 2; rg++) {
                    const char* p = Ab + (wr * 32 + rg * 16 + g) * 80 + kcl * 32 + t * 4;
                    a[rg][0] = *(const uint32_t*)p;
                    a[rg][1] = *(const uint32_t*)(p + 8 * 80);
                    a[rg][2] = *(const uint32_t*)(p + 16);
                    a[rg][3] = *(const uint32_t*)(p + 8 * 80 + 16);
                }
#pragma unroll
                for (int nb = 0; nb < 8; nb++) {
                    uint2 b = Bs[(kcl * 16 + wc * 8 + nb) * 32 + lane];
                    mma_bf16(acc[0][nb], a[0], b.x, b.y);
                    mma_bf16(acc[1][nb], a[1], b.x, b.y);
                }
            }
            __syncthreads();
            if (c < 8) {
                store_A(smem + (((c + 1) & 1) ? E_A1 : E_A0), tid, va);
                float4* dst = (float4*)(smem + (((c + 1) & 1) ? E_B1 : E_B0));
#pragma unroll
                for (int it = 0; it < 2; it++) dst[tid + it * 256] = vb[it];
                __syncthreads();
            }
        }
    }

    // ===== Epilogue 1: stage w2b (32KB) + h = silu(D1+be1) -> hbuf (bf16) ===
    {
        const float4* src = (const float4*)g_w2b;
        float4* dst = (float4*)(smem + E_A0);
#pragma unroll
        for (int it = 0; it < 8; it++) dst[tid + it * 256] = src[tid + it * 256];
    }
#pragma unroll
    for (int rg = 0; rg < 2; rg++) {
        int row0 = wr * 32 + rg * 16 + g;
#pragma unroll
        for (int nb = 0; nb < 8; nb++) {
            int col = wc * 64 + nb * 8 + 2 * t;
            float b0 = be1s[col], b1 = be1s[col + 1];
            uint32_t h0 = bf2(siluf(acc[rg][nb][0] + b0), siluf(acc[rg][nb][1] + b1));
            uint32_t h1 = bf2(siluf(acc[rg][nb][2] + b0), siluf(acc[rg][nb][3] + b1));
            *(uint32_t*)(hbuf + row0 * 272 + col * 2) = h0;
            *(uint32_t*)(hbuf + (row0 + 8) * 272 + col * 2) = h1;
            acc[rg][nb][0] = 0.f; acc[rg][nb][1] = 0.f;
            acc[rg][nb][2] = 0.f; acc[rg][nb][3] = 0.f;
        }
    }
    __syncthreads();

    // ================= GEMM2: K=128, sync-free ==============================
    {
        const uint2* B2 = (const uint2*)(smem + E_A0);
#pragma unroll
        for (int K16 = 0; K16 < 8; K16++) {
            uint32_t a[2][4];
#pragma unroll
            for (int rg = 0; rg < 2; rg++) {
                const char* p = hbuf + (wr * 32 + rg * 16 + g) * 272 + K16 * 32 + t * 4;
                a[rg][0] = *(const uint32_t*)p;
                a[rg][1] = *(const uint32_t*)(p + 8 * 272);
                a[rg][2] = *(const uint32_t*)(p + 16);
                a[rg][3] = *(const uint32_t*)(p + 8 * 272 + 16);
            }
#pragma unroll
            for (int nb = 0; nb < 8; nb++) {
                uint2 b = B2[(K16 * 16 + wc * 8 + nb) * 32 + lane];
                mma_bf16(acc[0][nb], a[0], b.x, b.y);
                mma_bf16(acc[1][nb], a[1], b.x, b.y);
            }
        }
    }
    __syncthreads();   // all reads of hbuf/staging done before mtile overwrite

    // ===== Epilogue 2: m = D2 + be2 -> mtile (f32) ==========================
#pragma unroll
    for (int rg = 0; rg < 2; rg++) {
        int row0 = wr * 32 + rg * 16 + g;
#pragma unroll
        for (int nb = 0; nb < 8; nb++) {
            int col = wc * 64 + nb * 8 + 2 * t;
            float b0 = be2s[col], b1 = be2s[col + 1];
            *(float2*)(mtile + row0 * 132 + col) =
                make_float2(acc[rg][nb][0] + b0, acc[rg][nb][1] + b1);
            *(float2*)(mtile + (row0 + 8) * 132 + col) =
                make_float2(acc[rg][nb][2] + b0, acc[rg][nb][3] + b1);
        }
    }
    __syncthreads();

    // gate
    if (tid < 128) {
        float s = 0.0f;
#pragma unroll 8
        for (int c = 0; c < 128; c++) s += mtile[tid * 132 + c] * wis[c];
        gates[tid] = sigmoidf_(s + bi[0]);
    }
    __syncthreads();

    // ===== SEGMENTED gated scatter (rows sorted by start within tile) ======
    {
        const int c  = tid & 127;        // column
        const int r0 = (tid >> 7) * 64;  // row half
        float accv = 0.0f;
        int sprev = starts[r0];
        for (int r = r0; r < r0 + 64; r++) {
            int s = starts[r];
            if (s != sprev) {
                atomicAdd(agg + (size_t)sprev * DM + c, accv);
                accv = 0.0f;
                sprev = s;
            }
            accv += mtile[r * 132 + c] * gates[r];
        }
        atomicAdd(agg + (size_t)sprev * DM + c, accv);
    }
}

// ===========================================================================
// Counting sort of edges by start node
// ===========================================================================
__global__ void hist_kernel(const int* __restrict__ ei) {
    int e = blockIdx.x * 256 + threadIdx.x;
    if (e < NE) atomicAdd(&g_hist[ei[e]], 1);
}

__global__ void scan_kernel() {
    const int CH = 49;                        // 1024*49 = 50176 >= NN
    __shared__ int ws[32];
    int t = threadIdx.x;
    int base = t * CH;
    int sum = 0;
#pragma unroll 7
    for (int i = 0; i < CH; i++) {
        int idx = base + i;
        if (idx < NN) sum += g_hist[idx];
    }
    int lane = t & 31, wid = t >> 5;
    int v = sum;
#pragma unroll
    for (int o = 1; o < 32; o <<= 1) {
        int u = __shfl_up_sync(0xffffffffu, v, o);
        if (lane >= o) v += u;
    }
    if (lane == 31) ws[wid] = v;
    __syncthreads();
    if (wid == 0) {
        int w = ws[lane];
#pragma unroll
        for (int o = 1; o < 32; o <<= 1) {
            int u = __shfl_up_sync(0xffffffffu, w, o);
            if (lane >= o) w += u;
        }
        ws[lane] = w;
    }
    __syncthreads();
    int pre = v - sum + (wid > 0 ? ws[wid - 1] : 0);
    int run = pre;
    for (int i = 0; i < CH; i++) {
        int idx = base + i;
        if (idx < NN) {
            int h = g_hist[idx];
            g_off[idx] = run;
            run += h;
        }
    }
}

__global__ void permute_kernel(const int* __restrict__ ei) {
    int e = blockIdx.x * 256 + threadIdx.x;
    if (e < NE) {
        int s = ei[e];
        int pos = g_off[s] + atomicAdd(&g_cnt[s], 1);
        g_perm[pos] = e;
    }
}

// ===========================================================================
// NODE KERNEL — bf16 mma, fp32 residual (validated in R7)
// ===========================================================================
#define N_A0  0
#define N_A1  10240
#define N_B0  20480
#define N_B1  28672
#define N_HB  36864
#define N_BN1 71680
#define N_BN2 72192
#define N_SMEM_BYTES 72704

__global__ void __launch_bounds__(256, 2)
node_kernel(const float* __restrict__ nf, const float* __restrict__ agg,
            const float* __restrict__ bn1, const float* __restrict__ bn2,
            float* __restrict__ out) {
    extern __shared__ char smem[];
    char*  hbuf  = smem + N_HB;
    float* bn1s  = (float*)(smem + N_BN1);
    float* bn2s  = (float*)(smem + N_BN2);

    const int tid  = threadIdx.x;
    const int lane = tid & 31;
    const int wid  = tid >> 5;
    const int wr   = wid & 3;
    const int wc   = wid >> 2;
    const int g    = lane >> 2;
    const int t    = lane & 3;
    const int n0   = blockIdx.x * 128;

    if (tid < 128) { bn1s[tid] = bn1[tid]; bn2s[tid] = bn2[tid]; }

    float acc[2][8][4];
#pragma unroll
    for (int rg = 0; rg < 2; rg++)
#pragma unroll
        for (int nb = 0; nb < 8; nb++)
#pragma unroll
            for (int i = 0; i < 4; i++) acc[rg][nb][i] = 0.0f;

    // ---------------- GEMM1: K=256, 8 chunks, double-buffered ---------------
    {
        float4 va[4], vb[2];
        const float4* w1 = (const float4*)g_wn1b;
#pragma unroll
        for (int it = 0; it < 4; it++) {
            int seg = tid + it * 256;
            int e = seg >> 3, s8 = seg & 7;
            int n = n0 + e; if (n >= NN) n = NN - 1;
            va[it] = *(const float4*)(nf + (size_t)n * D + s8 * 4);
        }
#pragma unroll
        for (int it = 0; it < 2; it++) vb[it] = w1[tid + it * 256];
        store_A(smem + N_A0, tid, va);
        {
            float4* dst = (float4*)(smem + N_B0);
#pragma unroll
            for (int it = 0; it < 2; it++) dst[tid + it * 256] = vb[it];
        }
        __syncthreads();

        for (int c = 0; c < 8; c++) {
            const int buf = c & 1;
            if (c < 7) {
                int cn = c + 1;
#pragma unroll
                for (int it = 0; it < 4; it++) {
                    int seg = tid + it * 256;
                    int e = seg >> 3, s8 = seg & 7;
                    int n = n0 + e; if (n >= NN) n = NN - 1;
                    const float* src = (cn < 4)
                        ? nf  + (size_t)n * D  + cn * 32 + s8 * 4
                        : agg + (size_t)n * DM + (cn - 4) * 32 + s8 * 4;
                    va[it] = *(const float4*)src;
                }
#pragma unroll
                for (int it = 0; it < 2; it++)
                    vb[it] = w1[cn * 512 + tid + it * 256];
            }
            const char* Ab = smem + (buf ? N_A1 : N_A0);
            const uint2* Bs = (const uint2*)(smem + (buf ? N_B1 : N_B0));
#pragma unroll
            for (int kcl = 0; kcl < 2; kcl++) {
                uint32_t a[2][4];
#pragma unroll
                for (int rg = 0; rg < 2; rg++) {
                    const char* p = Ab + (wr * 32 + rg * 16 + g) * 80 + kcl * 32 + t * 4;
                    a[rg][0] = *(const uint32_t*)p;
                    a[rg][1] = *(const uint32_t*)(p + 8 * 80);
                    a[rg][2] = *(const uint32_t*)(p + 16);
                    a[rg][3] = *(const uint32_t*)(p + 8 * 80 + 16);
                }
#pragma unroll
                for (int nb = 0; nb < 8; nb++) {
                    uint2 b = Bs[(kcl * 16 + wc * 8 + nb) * 32 + lane];
                    mma_bf16(acc[0][nb], a[0], b.x, b.y);
                    mma_bf16(acc[1][nb], a[1], b.x, b.y);
                }
            }
            __syncthreads();
            if (c < 7) {
                store_A(smem + (((c + 1) & 1) ? N_A1 : N_A0), tid, va);
                float4* dst = (float4*)(smem + (((c + 1) & 1) ? N_B1 : N_B0));
#pragma unroll
                for (int it = 0; it < 2; it++) dst[tid + it * 256] = vb[it];
                __syncthreads();
            }
        }
    }

    // ---- Epilogue 1: stage Wn2 + h = silu(D1+bn1) -> hbuf (bf16) ----------
    {
        const float4* src = (const float4*)g_wn2b;
        float4* dst = (float4*)(smem + N_A0);
#pragma unroll
        for (int it = 0; it < 8; it++) dst[tid + it * 256] = src[tid + it * 256];
    }
#pragma unroll
    for (int rg = 0; rg < 2; rg++) {
        int row0 = wr * 32 + rg * 16 + g;
#pragma unroll
        for (int nb = 0; nb < 8; nb++) {
            int col = wc * 64 + nb * 8 + 2 * t;
            float b0 = bn1s[col], b1 = bn1s[col + 1];
            uint32_t h0 = bf2(siluf(acc[rg][nb][0] + b0), siluf(acc[rg][nb][1] + b1));
            uint32_t h1 = bf2(siluf(acc[rg][nb][2] + b0), siluf(acc[rg][nb][3] + b1));
            *(uint32_t*)(hbuf + row0 * 272 + col * 2) = h0;
            *(uint32_t*)(hbuf + (row0 + 8) * 272 + col * 2) = h1;
            acc[rg][nb][0] = 0.f; acc[rg][nb][1] = 0.f;
            acc[rg][nb][2] = 0.f; acc[rg][nb][3] = 0.f;
        }
    }
    __syncthreads();

    // ---------------- GEMM2: K=128, sync-free ------------------------------
    {
        const uint2* B2 = (const uint2*)(smem + N_A0);
#pragma unroll
        for (int K16 = 0; K16 < 8; K16++) {
            uint32_t a[2][4];
#pragma unroll
            for (int rg = 0; rg < 2; rg++) {
                const char* p = hbuf + (wr * 32 + rg * 16 + g) * 272 + K16 * 32 + t * 4;
                a[rg][0] = *(const uint32_t*)p;
                a[rg][1] = *(const uint32_t*)(p + 8 * 272);
                a[rg][2] = *(const uint32_t*)(p + 16);
                a[rg][3] = *(const uint32_t*)(p + 8 * 272 + 16);
            }
#pragma unroll
            for (int nb = 0; nb < 8; nb++) {
                uint2 b = B2[(K16 * 16 + wc * 8 + nb) * 32 + lane];
                mma_bf16(acc[0][nb], a[0], b.x, b.y);
                mma_bf16(acc[1][nb], a[1], b.x, b.y);
            }
        }
    }

    // ---------------- Epilogue 2: out = nf + D2 + bn2 -----------------------
#pragma unroll
    for (int rg = 0; rg < 2; rg++) {
        int r0 = wr * 32 + rg * 16 + g;
#pragma unroll
        for (int h = 0; h < 2; h++) {
            int n = n0 + r0 + 8 * h;
            if (n >= NN) continue;
#pragma unroll
            for (int nb = 0; nb < 8; nb++) {
                int col = wc * 64 + nb * 8 + 2 * t;
                float2 res = *(const float2*)(nf + (size_t)n * D + col);
                float a0 = (h ? acc[rg][nb][2] : acc[rg][nb][0]) + bn2s[col] + res.x;
                float a1 = (h ? acc[rg][nb][3] : acc[rg][nb][1]) + bn2s[col + 1] + res.y;
                *(float2*)(out + (size_t)n * D + col) = make_float2(a0, a1);
            }
        }
    }
}

// ---------------------------------------------------------------------------
// Weight prep
// ---------------------------------------------------------------------------
__device__ __forceinline__ uint2 pack_frag(const float* W, int idx, int K) {
    int lane = idx & 31;
    int nbk = idx >> 5;
    int k0 = (nbk >> 4) * 16;
    int n = (nbk & 15) * 8 + (lane >> 2);
    int t2 = (lane & 3) * 2;
    float v00 = (k0 + t2     < K) ? W[(size_t)(k0 + t2) * 128 + n] : 0.0f;
    float v01 = (k0 + t2 + 1 < K) ? W[(size_t)(k0 + t2 + 1) * 128 + n] : 0.0f;
    float v10 = (k0 + t2 + 8 < K) ? W[(size_t)(k0 + t2 + 8) * 128 + n] : 0.0f;
    float v11 = (k0 + t2 + 9 < K) ? W[(size_t)(k0 + t2 + 9) * 128 + n] : 0.0f;
    return make_uint2(bf2(v00, v01), bf2(v10, v11));
}

__global__ void prep_kernel(const float* __restrict__ We1, const float* __restrict__ We2,
                            const float* __restrict__ Wn1, const float* __restrict__ Wn2) {
    int i = blockIdx.x * 256 + threadIdx.x;
    if (i < 9216)        g_w1b[i] = pack_frag(We1, i, 272);
    else if (i < 13312)  g_w2b[i - 9216] = pack_frag(We2, i - 9216, 128);
    else if (i < 21504)  g_wn1b[i - 13312] = pack_frag(Wn1, i - 13312, 256);
    else if (i < 25600)  g_wn2b[i - 21504] = pack_frag(Wn2, i - 21504, 128);
}

// ---------------------------------------------------------------------------
__global__ void idx_to_float_kernel(const int4* __restrict__ ei,
                                    float4* __restrict__ out) {
    int i = blockIdx.x * blockDim.x + threadIdx.x;
    if (i < (2 * NE) / 4) {
        int4 v = ei[i];
        out[i] = make_float4((float)v.x, (float)v.y, (float)v.z, (float)v.w);
    }
}

// ---------------------------------------------------------------------------
extern "C" void kernel_launch(void* const* d_in, const int* in_sizes, int n_in,
                              void* d_out, int out_size) {
    const float* nf  = (const float*)d_in[0];
    const int*   ei  = (const int*)d_in[1];
    const float* ef  = (const float*)d_in[2];
    const float* We1 = (const float*)d_in[3];
    const float* be1 = (const float*)d_in[4];
    const float* We2 = (const float*)d_in[5];
    const float* be2 = (const float*)d_in[6];
    const float* Wi  = (const float*)d_in[7];
    const float* bi  = (const float*)d_in[8];
    const float* Wn1 = (const float*)d_in[9];
    const float* bn1 = (const float*)d_in[10];
    const float* Wn2 = (const float*)d_in[11];
    const float* bn2 = (const float*)d_in[12];
    float* out = (float*)d_out;

    cudaFuncSetAttribute(edge_kernel, cudaFuncAttributeMaxDynamicSharedMemorySize, E_SMEM_BYTES);
    cudaFuncSetAttribute(node_kernel, cudaFuncAttributeMaxDynamicSharedMemorySize, N_SMEM_BYTES);

    void *aggp, *histp, *cntp;
    cudaGetSymbolAddress(&aggp, g_agg);
    cudaGetSymbolAddress(&histp, g_hist);
    cudaGetSymbolAddress(&cntp, g_cnt);
    cudaMemsetAsync(aggp, 0, (size_t)NN * DM * sizeof(float));
    cudaMemsetAsync(histp, 0, NN * sizeof(int));
    cudaMemsetAsync(cntp, 0, NN * sizeof(int));

    prep_kernel<<<(25600 + 255) / 256, 256>>>(We1, We2, Wn1, Wn2);
    hist_kernel<<<NE / 256, 256>>>(ei);
    scan_kernel<<<1, 1024>>>();
    permute_kernel<<<NE / 256, 256>>>(ei);

    edge_kernel<<<NE / 128, 256, E_SMEM_BYTES>>>(nf, ei, ef, be1, be2, Wi, bi,
                                                 (float*)aggp);
    node_kernel<<<(NN + 127) / 128, 256, N_SMEM_BYTES>>>(nf, (const float*)aggp,
                                                         bn1, bn2, out);

    idx_to_float_kernel<<<((2 * NE / 4) + 255) / 256, 256>>>(
        (const int4*)ei, (float4*)(out + (size_t)NN * D));
    cudaMemcpyAsync(out + (size_t)NN * D + 2ull * NE, d_in[2],
                    (size_t)NE * DE * sizeof(float), cudaMemcpyDeviceToDevice);
}

// round 9
// speedup vs baseline: 1.1761x; 1.0009x over previous
#include <cuda_runtime.h>
#include <cstdint>

#define NN 50000
#define NE 800000
#define D  128
#define DE 16
#define DM 128

// ---------------------------------------------------------------------------
// Global scratch
// ---------------------------------------------------------------------------
__device__ float g_agg[NN * DM];
__device__ float g_P[NN * 256];       // P = nf @ [W_s | W_e]  (f32)
__device__ int   g_hist[NN];
__device__ int   g_off[NN];
__device__ int   g_cnt[NN];
__device__ int   g_perm[NE];
// bf16 fragment-packed weights: uint2{b0,b1} per (K16, nb, lane)
__device__ __align__(16) uint2 g_wsb[8 * 16 * 32];    // We1 rows 0..127
__device__ __align__(16) uint2 g_web[8 * 16 * 32];    // We1 rows 128..255
__device__ __align__(16) uint2 g_wefb[2 * 16 * 32];   // We1 rows 256..271 (pad 32)
__device__ __align__(16) uint2 g_w2b[8 * 16 * 32];    // We2, K=128
__device__ __align__(16) uint2 g_wn1b[16 * 16 * 32];  // Wn1, K=256
__device__ __align__(16) uint2 g_wn2b[8 * 16 * 32];   // Wn2, K=128

// ---------------------------------------------------------------------------
// helpers
// ---------------------------------------------------------------------------
__device__ __forceinline__ float siluf(float x) { return x / (1.0f + __expf(-x)); }
__device__ __forceinline__ float sigmoidf_(float x) { return 1.0f / (1.0f + __expf(-x)); }

__device__ __forceinline__ uint32_t bf2(float lo, float hi) {
    uint32_t r;
    asm("cvt.rn.bf16x2.f32 %0, %1, %2;" : "=r"(r) : "f"(hi), "f"(lo));
    return r;
}
__device__ __forceinline__ void mma_bf16(float c[4], const uint32_t a[4],
                                         uint32_t b0, uint32_t b1) {
    asm volatile("mma.sync.aligned.m16n8k16.row.col.f32.bf16.bf16.f32 "
        "{%0,%1,%2,%3}, {%4,%5,%6,%7}, {%8,%9}, {%0,%1,%2,%3};"
        : "+f"(c[0]), "+f"(c[1]), "+f"(c[2]), "+f"(c[3])
        : "r"(a[0]), "r"(a[1]), "r"(a[2]), "r"(a[3]), "r"(b0), "r"(b1));
}

// ---------------------------------------------------------------------------
// Edge kernel SMEM layout (bytes)
//   R1 (67584): S f32 [128][132]  ->  W2S (32768)  ->  mtile f32 [128][132]
//   R2 (34816): Aef (10240, early) -> hbuf bf16 [128 x 272B]
//   R3 (8192):  Wef
// ---------------------------------------------------------------------------
#define E_R1     0
#define E_HB     67584
#define E_WEF    102400
#define E_MISC   110592
#define E_STARTS (E_MISC)
#define E_ENDS   (E_MISC + 512)
#define E_EIDX   (E_MISC + 1024)
#define E_BE1    (E_MISC + 1536)
#define E_BE2    (E_MISC + 2048)
#define E_WIS    (E_MISC + 2560)
#define E_GATES  (E_MISC + 3072)
#define E_SMEM_BYTES (E_MISC + 3584)   // 114176

__device__ __forceinline__ void store_A(char* Ab, int tid, const float4 va[4]) {
#pragma unroll
    for (int it = 0; it < 4; it++) {
        int seg = tid + it * 256;
        int e = seg >> 3, s8 = seg & 7;
        uint2 u = make_uint2(bf2(va[it].x, va[it].y), bf2(va[it].z, va[it].w));
        *(uint2*)(Ab + e * 80 + s8 * 8) = u;
    }
}

// ---------------------------------------------------------------------------
// Edge kernel: P-gather-add + tiny ef MMA -> silu -> GEMM2 -> gate -> scatter
// ---------------------------------------------------------------------------
__global__ void __launch_bounds__(256, 2)
edge_kernel(const float* __restrict__ nf, const int* __restrict__ ei,
            const float* __restrict__ ef, const float* __restrict__ P,
            const float* __restrict__ be1, const float* __restrict__ be2,
            const float* __restrict__ Wi, const float* __restrict__ bi,
            float* __restrict__ agg) {
    extern __shared__ char smem[];
    float* S      = (float*)(smem + E_R1);        // stride 132
    float* mtile  = (float*)(smem + E_R1);        // late-phase alias
    char*  hbuf   = smem + E_HB;                  // bf16, 272B stride
    char*  Aef    = smem + E_HB;                  // early-phase alias
    int*   starts = (int*)(smem + E_STARTS);
    int*   ends   = (int*)(smem + E_ENDS);
    int*   eidx   = (int*)(smem + E_EIDX);
    float* be1s   = (float*)(smem + E_BE1);
    float* be2s   = (float*)(smem + E_BE2);
    float* wis    = (float*)(smem + E_WIS);
    float* gates  = (float*)(smem + E_GATES);

    const int tid  = threadIdx.x;
    const int lane = tid & 31;
    const int wid  = tid >> 5;
    const int wr   = wid & 3;
    const int wc   = wid >> 2;
    const int g    = lane >> 2;
    const int t    = lane & 3;
    const int e0   = blockIdx.x * 128;

    if (tid < 128) {
        int e = g_perm[e0 + tid];
        eidx[tid]   = e;
        starts[tid] = ei[e];
        ends[tid]   = ei[NE + e];
        be1s[tid]   = be1[tid];
        be2s[tid]   = be2[tid];
        wis[tid]    = Wi[tid];
    }
    __syncthreads();

    // ---- stage Wef + gather ef tile into Aef ----
    {
        const float4* src = (const float4*)g_wefb;
        float4* dst = (float4*)(smem + E_WEF);
#pragma unroll
        for (int it = 0; it < 2; it++) dst[tid + it * 256] = src[tid + it * 256];
        float4 va[4];
#pragma unroll
        for (int it = 0; it < 4; it++) {
            int seg = tid + it * 256;
            int e = seg >> 3, s8 = seg & 7;
            va[it] = (s8 < 4) ? *(const float4*)(ef + (size_t)eidx[e] * DE + s8 * 4)
                              : make_float4(0.f, 0.f, 0.f, 0.f);
        }
        store_A(Aef, tid, va);
    }
    __syncthreads();

    float acc[2][8][4];
#pragma unroll
    for (int rg = 0; rg < 2; rg++)
#pragma unroll
        for (int nb = 0; nb < 8; nb++)
#pragma unroll
            for (int i = 0; i < 4; i++) acc[rg][nb][i] = 0.0f;

    // ---- ef MMA (K=32 padded, 2 K16 blocks) ----
    {
        const uint2* Bs = (const uint2*)(smem + E_WEF);
#pragma unroll
        for (int kcl = 0; kcl < 2; kcl++) {
            uint32_t a[2][4];
#pragma unroll
            for (int rg = 0; rg < 2; rg++) {
                const char* p = Aef + (wr * 32 + rg * 16 + g) * 80 + kcl * 32 + t * 4;
                a[rg][0] = *(const uint32_t*)p;
                a[rg][1] = *(const uint32_t*)(p + 8 * 80);
                a[rg][2] = *(const uint32_t*)(p + 16);
                a[rg][3] = *(const uint32_t*)(p + 8 * 80 + 16);
            }
#pragma unroll
            for (int nb = 0; nb < 8; nb++) {
                uint2 b = Bs[(kcl * 16 + wc * 8 + nb) * 32 + lane];
                mma_bf16(acc[0][nb], a[0], b.x, b.y);
                mma_bf16(acc[1][nb], a[1], b.x, b.y);
            }
        }
    }

    // ---- P gather-add: S[row][col] = P_s[start] + P_e[end] ----
#pragma unroll
    for (int it = 0; it < 16; it++) {
        int seg = tid + it * 256;
        int row = seg >> 5, c4 = (seg & 31) * 4;
        int s = starts[row], e_ = ends[row];
        float4 a = *(const float4*)(P + (size_t)s * 256 + c4);
        float4 b = *(const float4*)(P + (size_t)e_ * 256 + 128 + c4);
        *(float4*)(S + row * 132 + c4) =
            make_float4(a.x + b.x, a.y + b.y, a.z + b.z, a.w + b.w);
    }
    __syncthreads();

    // ---- Epilogue 1: h = silu(acc + S + be1) -> hbuf bf16 (over Aef) ----
#pragma unroll
    for (int rg = 0; rg < 2; rg++) {
        int r0 = wr * 32 + rg * 16 + g;
#pragma unroll
        for (int nb = 0; nb < 8; nb++) {
            int col = wc * 64 + nb * 8 + 2 * t;
            float2 s0 = *(const float2*)(S + r0 * 132 + col);
            float2 s1 = *(const float2*)(S + (r0 + 8) * 132 + col);
            float b0 = be1s[col], b1 = be1s[col + 1];
            uint32_t h0 = bf2(siluf(acc[rg][nb][0] + s0.x + b0),
                              siluf(acc[rg][nb][1] + s0.y + b1));
            uint32_t h1 = bf2(siluf(acc[rg][nb][2] + s1.x + b0),
                              siluf(acc[rg][nb][3] + s1.y + b1));
            *(uint32_t*)(hbuf + r0 * 272 + col * 2) = h0;
            *(uint32_t*)(hbuf + (r0 + 8) * 272 + col * 2) = h1;
            acc[rg][nb][0] = 0.f; acc[rg][nb][1] = 0.f;
            acc[rg][nb][2] = 0.f; acc[rg][nb][3] = 0.f;
        }
    }
    __syncthreads();

    // ---- stage W2 into R1 (S dead) ----
    {
        const float4* src = (const float4*)g_w2b;
        float4* dst = (float4*)(smem + E_R1);
#pragma unroll
        for (int it = 0; it < 8; it++) dst[tid + it * 256] = src[tid + it * 256];
    }
    __syncthreads();

    // ---- GEMM2: D2 = h @ We2 (K=128, sync-free) ----
    {
        const uint2* B2 = (const uint2*)(smem + E_R1);
#pragma unroll
        for (int K16 = 0; K16 < 8; K16++) {
            uint32_t a[2][4];
#pragma unroll
            for (int rg = 0; rg < 2; rg++) {
                const char* p = hbuf + (wr * 32 + rg * 16 + g) * 272 + K16 * 32 + t * 4;
                a[rg][0] = *(const uint32_t*)p;
                a[rg][1] = *(const uint32_t*)(p + 8 * 272);
                a[rg][2] = *(const uint32_t*)(p + 16);
                a[rg][3] = *(const uint32_t*)(p + 8 * 272 + 16);
            }
#pragma unroll
            for (int nb = 0; nb < 8; nb++) {
                uint2 b = B2[(K16 * 16 + wc * 8 + nb) * 32 + lane];
                mma_bf16(acc[0][nb], a[0], b.x, b.y);
                mma_bf16(acc[1][nb], a[1], b.x, b.y);
            }
        }
    }
    __syncthreads();   // W2S reads done before mtile overwrite

    // ---- Epilogue 2: m = D2 + be2 -> mtile ----
#pragma unroll
    for (int rg = 0; rg < 2; rg++) {
        int r0 = wr * 32 + rg * 16 + g;
#pragma unroll
        for (int nb = 0; nb < 8; nb++) {
            int col = wc * 64 + nb * 8 + 2 * t;
            float b0 = be2s[col], b1 = be2s[col + 1];
            *(float2*)(mtile + r0 * 132 + col) =
                make_float2(acc[rg][nb][0] + b0, acc[rg][nb][1] + b1);
            *(float2*)(mtile + (r0 + 8) * 132 + col) =
                make_float2(acc[rg][nb][2] + b0, acc[rg][nb][3] + b1);
        }
    }
    __syncthreads();

    // gate
    if (tid < 128) {
        float s = 0.0f;
#pragma unroll 8
        for (int c = 0; c < 128; c++) s += mtile[tid * 132 + c] * wis[c];
        gates[tid] = sigmoidf_(s + bi[0]);
    }
    __syncthreads();

    // segmented gated scatter (rows sorted by start)
    {
        const int c  = tid & 127;
        const int r0 = (tid >> 7) * 64;
        float accv = 0.0f;
        int sprev = starts[r0];
        for (int r = r0; r < r0 + 64; r++) {
            int s = starts[r];
            if (s != sprev) {
                atomicAdd(agg + (size_t)sprev * DM + c, accv);
                accv = 0.0f;
                sprev = s;
            }
            accv += mtile[r * 132 + c] * gates[r];
        }
        atomicAdd(agg + (size_t)sprev * DM + c, accv);
    }
}

// ===========================================================================
// P KERNEL: P[:, half*128 : +128] = nf @ (half ? W_e : W_s)
// ===========================================================================
#define P_A 0           // 128 rows x 272B bf16 = 34816
#define P_B 34816       // 32768
#define P_SMEM_BYTES 67584

__global__ void __launch_bounds__(256, 2)
p_kernel(const float* __restrict__ nf, float* __restrict__ P) {
    extern __shared__ char smem[];
    char* Ab = smem + P_A;

    const int tid  = threadIdx.x;
    const int lane = tid & 31;
    const int wid  = tid >> 5;
    const int wr   = wid & 3;
    const int wc   = wid >> 2;
    const int g    = lane >> 2;
    const int t    = lane & 3;
    const int n0   = blockIdx.x * 128;
    const int half = blockIdx.y;

    // stage B (whole 32KB)
    {
        const float4* src = (const float4*)(half ? g_web : g_wsb);
        float4* dst = (float4*)(smem + P_B);
#pragma unroll
        for (int it = 0; it < 8; it++) dst[tid + it * 256] = src[tid + it * 256];
    }
    // stage A: nf tile as bf16, stride 272
#pragma unroll
    for (int it = 0; it < 8; it++) {
        int seg = tid + it * 256;
        int row = seg >> 4, c8 = seg & 15;
        int n = n0 + row; if (n >= NN) n = NN - 1;
        float4 f0 = *(const float4*)(nf + (size_t)n * D + c8 * 8);
        float4 f1 = *(const float4*)(nf + (size_t)n * D + c8 * 8 + 4);
        uint4 u = make_uint4(bf2(f0.x, f0.y), bf2(f0.z, f0.w),
                             bf2(f1.x, f1.y), bf2(f1.z, f1.w));
        *(uint4*)(Ab + row * 272 + c8 * 16) = u;
    }
    __syncthreads();

    float acc[2][8][4];
#pragma unroll
    for (int rg = 0; rg < 2; rg++)
#pragma unroll
        for (int nb = 0; nb < 8; nb++)
#pragma unroll
            for (int i = 0; i < 4; i++) acc[rg][nb][i] = 0.0f;

    {
        const uint2* Bs = (const uint2*)(smem + P_B);
#pragma unroll
        for (int K16 = 0; K16 < 8; K16++) {
            uint32_t a[2][4];
#pragma unroll
            for (int rg = 0; rg < 2; rg++) {
                const char* p = Ab + (wr * 32 + rg * 16 + g) * 272 + K16 * 32 + t * 4;
                a[rg][0] = *(const uint32_t*)p;
                a[rg][1] = *(const uint32_t*)(p + 8 * 272);
                a[rg][2] = *(const uint32_t*)(p + 16);
                a[rg][3] = *(const uint32_t*)(p + 8 * 272 + 16);
            }
#pragma unroll
            for (int nb = 0; nb < 8; nb++) {
                uint2 b = Bs[(K16 * 16 + wc * 8 + nb) * 32 + lane];
                mma_bf16(acc[0][nb], a[0], b.x, b.y);
                mma_bf16(acc[1][nb], a[1], b.x, b.y);
            }
        }
    }

#pragma unroll
    for (int rg = 0; rg < 2; rg++) {
        int r0 = wr * 32 + rg * 16 + g;
#pragma unroll
        for (int h = 0; h < 2; h++) {
            int n = n0 + r0 + 8 * h;
            if (n >= NN) continue;
#pragma unroll
            for (int nb = 0; nb < 8; nb++) {
                int col = wc * 64 + nb * 8 + 2 * t;
                float a0 = h ? acc[rg][nb][2] : acc[rg][nb][0];
                float a1 = h ? acc[rg][nb][3] : acc[rg][nb][1];
                *(float2*)(P + (size_t)n * 256 + half * 128 + col) = make_float2(a0, a1);
            }
        }
    }
}

// ===========================================================================
// Counting sort of edges by start node
// ===========================================================================
__global__ void hist_kernel(const int* __restrict__ ei) {
    int e = blockIdx.x * 256 + threadIdx.x;
    if (e < NE) atomicAdd(&g_hist[ei[e]], 1);
}

__global__ void scan_kernel() {
    const int CH = 49;
    __shared__ int ws[32];
    int t = threadIdx.x;
    int base = t * CH;
    int sum = 0;
#pragma unroll 7
    for (int i = 0; i < CH; i++) {
        int idx = base + i;
        if (idx < NN) sum += g_hist[idx];
    }
    int lane = t & 31, wid = t >> 5;
    int v = sum;
#pragma unroll
    for (int o = 1; o < 32; o <<= 1) {
        int u = __shfl_up_sync(0xffffffffu, v, o);
        if (lane >= o) v += u;
    }
    if (lane == 31) ws[wid] = v;
    __syncthreads();
    if (wid == 0) {
        int w = ws[lane];
#pragma unroll
        for (int o = 1; o < 32; o <<= 1) {
            int u = __shfl_up_sync(0xffffffffu, w, o);
            if (lane >= o) w += u;
        }
        ws[lane] = w;
    }
    __syncthreads();
    int pre = v - sum + (wid > 0 ? ws[wid - 1] : 0);
    int run = pre;
    for (int i = 0; i < CH; i++) {
        int idx = base + i;
        if (idx < NN) {
            int h = g_hist[idx];
            g_off[idx] = run;
            run += h;
        }
    }
}

__global__ void permute_kernel(const int* __restrict__ ei) {
    int e = blockIdx.x * 256 + threadIdx.x;
    if (e < NE) {
        int s = ei[e];
        int pos = g_off[s] + atomicAdd(&g_cnt[s], 1);
        g_perm[pos] = e;
    }
}

// ===========================================================================
// NODE KERNEL — bf16 mma, fp32 residual (validated R7/R8)
// ===========================================================================
#define N_A0  0
#define N_A1  10240
#define N_B0  20480
#define N_B1  28672
#define N_HB  36864
#define N_BN1 71680
#define N_BN2 72192
#define N_SMEM_BYTES 72704

__global__ void __launch_bounds__(256, 2)
node_kernel(const float* __restrict__ nf, const float* __restrict__ agg,
            const float* __restrict__ bn1, const float* __restrict__ bn2,
            float* __restrict__ out) {
    extern __shared__ char smem[];
    char*  hbuf  = smem + N_HB;
    float* bn1s  = (float*)(smem + N_BN1);
    float* bn2s  = (float*)(smem + N_BN2);

    const int tid  = threadIdx.x;
    const int lane = tid & 31;
    const int wid  = tid >> 5;
    const int wr   = wid & 3;
    const int wc   = wid >> 2;
    const int g    = lane >> 2;
    const int t    = lane & 3;
    const int n0   = blockIdx.x * 128;

    if (tid < 128) { bn1s[tid] = bn1[tid]; bn2s[tid] = bn2[tid]; }

    float acc[2][8][4];
#pragma unroll
    for (int rg = 0; rg < 2; rg++)
#pragma unroll
        for (int nb = 0; nb < 8; nb++)
#pragma unroll
            for (int i = 0; i < 4; i++) acc[rg][nb][i] = 0.0f;

    {
        float4 va[4], vb[2];
        const float4* w1 = (const float4*)g_wn1b;
#pragma unroll
        for (int it = 0; it < 4; it++) {
            int seg = tid + it * 256;
            int e = seg >> 3, s8 = seg & 7;
            int n = n0 + e; if (n >= NN) n = NN - 1;
            va[it] = *(const float4*)(nf + (size_t)n * D + s8 * 4);
        }
#pragma unroll
        for (int it = 0; it < 2; it++) vb[it] = w1[tid + it * 256];
        store_A(smem + N_A0, tid, va);
        {
            float4* dst = (float4*)(smem + N_B0);
#pragma unroll
            for (int it = 0; it < 2; it++) dst[tid + it * 256] = vb[it];
        }
        __syncthreads();

        for (int c = 0; c < 8; c++) {
            const int buf = c & 1;
            if (c < 7) {
                int cn = c + 1;
#pragma unroll
                for (int it = 0; it < 4; it++) {
                    int seg = tid + it * 256;
                    int e = seg >> 3, s8 = seg & 7;
                    int n = n0 + e; if (n >= NN) n = NN - 1;
                    const float* src = (cn < 4)
                        ? nf  + (size_t)n * D  + cn * 32 + s8 * 4
                        : agg + (size_t)n * DM + (cn - 4) * 32 + s8 * 4;
                    va[it] = *(const float4*)src;
                }
#pragma unroll
                for (int it = 0; it < 2; it++)
                    vb[it] = w1[cn * 512 + tid + it * 256];
            }
            const char* Ab = smem + (buf ? N_A1 : N_A0);
            const uint2* Bs = (const uint2*)(smem + (buf ? N_B1 : N_B0));
#pragma unroll
            for (int kcl = 0; kcl < 2; kcl++) {
                uint32_t a[2][4];
#pragma unroll
                for (int rg = 0; rg < 2; rg++) {
                    const char* p = Ab + (wr * 32 + rg * 16 + g) * 80 + kcl * 32 + t * 4;
                    a[rg][0] = *(const uint32_t*)p;
                    a[rg][1] = *(const uint32_t*)(p + 8 * 80);
                    a[rg][2] = *(const uint32_t*)(p + 16);
                    a[rg][3] = *(const uint32_t*)(p + 8 * 80 + 16);
                }
#pragma unroll
                for (int nb = 0; nb < 8; nb++) {
                    uint2 b = Bs[(kcl * 16 + wc * 8 + nb) * 32 + lane];
                    mma_bf16(acc[0][nb], a[0], b.x, b.y);
                    mma_bf16(acc[1][nb], a[1], b.x, b.y);
                }
            }
            __syncthreads();
            if (c < 7) {
                store_A(smem + (((c + 1) & 1) ? N_A1 : N_A0), tid, va);
                float4* dst = (float4*)(smem + (((c + 1) & 1) ? N_B1 : N_B0));
#pragma unroll
                for (int it = 0; it < 2; it++) dst[tid + it * 256] = vb[it];
                __syncthreads();
            }
        }
    }

    {
        const float4* src = (const float4*)g_wn2b;
        float4* dst = (float4*)(smem + N_A0);
#pragma unroll
        for (int it = 0; it < 8; it++) dst[tid + it * 256] = src[tid + it * 256];
    }
#pragma unroll
    for (int rg = 0; rg < 2; rg++) {
        int row0 = wr * 32 + rg * 16 + g;
#pragma unroll
        for (int nb = 0; nb < 8; nb++) {
            int col = wc * 64 + nb * 8 + 2 * t;
            float b0 = bn1s[col], b1 = bn1s[col + 1];
            uint32_t h0 = bf2(siluf(acc[rg][nb][0] + b0), siluf(acc[rg][nb][1] + b1));
            uint32_t h1 = bf2(siluf(acc[rg][nb][2] + b0), siluf(acc[rg][nb][3] + b1));
            *(uint32_t*)(hbuf + row0 * 272 + col * 2) = h0;
            *(uint32_t*)(hbuf + (row0 + 8) * 272 + col * 2) = h1;
            acc[rg][nb][0] = 0.f; acc[rg][nb][1] = 0.f;
            acc[rg][nb][2] = 0.f; acc[rg][nb][3] = 0.f;
        }
    }
    __syncthreads();

    {
        const uint2* B2 = (const uint2*)(smem + N_A0);
#pragma unroll
        for (int K16 = 0; K16 < 8; K16++) {
            uint32_t a[2][4];
#pragma unroll
            for (int rg = 0; rg < 2; rg++) {
                const char* p = hbuf + (wr * 32 + rg * 16 + g) * 272 + K16 * 32 + t * 4;
                a[rg][0] = *(const uint32_t*)p;
                a[rg][1] = *(const uint32_t*)(p + 8 * 272);
                a[rg][2] = *(const uint32_t*)(p + 16);
                a[rg][3] = *(const uint32_t*)(p + 8 * 272 + 16);
            }
#pragma unroll
            for (int nb = 0; nb < 8; nb++) {
                uint2 b = B2[(K16 * 16 + wc * 8 + nb) * 32 + lane];
                mma_bf16(acc[0][nb], a[0], b.x, b.y);
                mma_bf16(acc[1][nb], a[1], b.x, b.y);
            }
        }
    }

#pragma unroll
    for (int rg = 0; rg < 2; rg++) {
        int r0 = wr * 32 + rg * 16 + g;
#pragma unroll
        for (int h = 0; h < 2; h++) {
            int n = n0 + r0 + 8 * h;
            if (n >= NN) continue;
#pragma unroll
            for (int nb = 0; nb < 8; nb++) {
                int col = wc * 64 + nb * 8 + 2 * t;
                float2 res = *(const float2*)(nf + (size_t)n * D + col);
                float a0 = (h ? acc[rg][nb][2] : acc[rg][nb][0]) + bn2s[col] + res.x;
                float a1 = (h ? acc[rg][nb][3] : acc[rg][nb][1]) + bn2s[col + 1] + res.y;
                *(float2*)(out + (size_t)n * D + col) = make_float2(a0, a1);
            }
        }
    }
}

// ---------------------------------------------------------------------------
// Weight prep
// ---------------------------------------------------------------------------
__device__ __forceinline__ uint2 pack_frag2(const float* W, int idx, int row0, int rowlim) {
    int lane = idx & 31;
    int nbk = idx >> 5;
    int k0 = (nbk >> 4) * 16;
    int n = (nbk & 15) * 8 + (lane >> 2);
    int t2 = (lane & 3) * 2;
    int r = row0 + k0 + t2;
    float v00 = (r     < rowlim) ? W[(size_t)r * 128 + n] : 0.0f;
    float v01 = (r + 1 < rowlim) ? W[(size_t)(r + 1) * 128 + n] : 0.0f;
    float v10 = (r + 8 < rowlim) ? W[(size_t)(r + 8) * 128 + n] : 0.0f;
    float v11 = (r + 9 < rowlim) ? W[(size_t)(r + 9) * 128 + n] : 0.0f;
    return make_uint2(bf2(v00, v01), bf2(v10, v11));
}

__global__ void prep_kernel(const float* __restrict__ We1, const float* __restrict__ We2,
                            const float* __restrict__ Wn1, const float* __restrict__ Wn2) {
    int i = blockIdx.x * 256 + threadIdx.x;
    if (i < 4096)        g_wsb[i] = pack_frag2(We1, i, 0, 272);
    else if (i < 8192)   g_web[i - 4096] = pack_frag2(We1, i - 4096, 128, 272);
    else if (i < 9216)   g_wefb[i - 8192] = pack_frag2(We1, i - 8192, 256, 272);
    else if (i < 13312)  g_w2b[i - 9216] = pack_frag2(We2, i - 9216, 0, 128);
    else if (i < 21504)  g_wn1b[i - 13312] = pack_frag2(Wn1, i - 13312, 0, 256);
    else if (i < 25600)  g_wn2b[i - 21504] = pack_frag2(Wn2, i - 21504, 0, 128);
}

// ---------------------------------------------------------------------------
__global__ void idx_to_float_kernel(const int4* __restrict__ ei,
                                    float4* __restrict__ out) {
    int i = blockIdx.x * blockDim.x + threadIdx.x;
    if (i < (2 * NE) / 4) {
        int4 v = ei[i];
        out[i] = make_float4((float)v.x, (float)v.y, (float)v.z, (float)v.w);
    }
}

// ---------------------------------------------------------------------------
extern "C" void kernel_launch(void* const* d_in, const int* in_sizes, int n_in,
                              void* d_out, int out_size) {
    const float* nf  = (const float*)d_in[0];
    const int*   ei  = (const int*)d_in[1];
    const float* ef  = (const float*)d_in[2];
    const float* We1 = (const float*)d_in[3];
    const float* be1 = (const float*)d_in[4];
    const float* We2 = (const float*)d_in[5];
    const float* be2 = (const float*)d_in[6];
    const float* Wi  = (const float*)d_in[7];
    const float* bi  = (const float*)d_in[8];
    const float* Wn1 = (const float*)d_in[9];
    const float* bn1 = (const float*)d_in[10];
    const float* Wn2 = (const float*)d_in[11];
    const float* bn2 = (const float*)d_in[12];
    float* out = (float*)d_out;

    cudaFuncSetAttribute(edge_kernel, cudaFuncAttributeMaxDynamicSharedMemorySize, E_SMEM_BYTES);
    cudaFuncSetAttribute(node_kernel, cudaFuncAttributeMaxDynamicSharedMemorySize, N_SMEM_BYTES);
    cudaFuncSetAttribute(p_kernel, cudaFuncAttributeMaxDynamicSharedMemorySize, P_SMEM_BYTES);

    void *aggp, *histp, *cntp, *pp;
    cudaGetSymbolAddress(&aggp, g_agg);
    cudaGetSymbolAddress(&histp, g_hist);
    cudaGetSymbolAddress(&cntp, g_cnt);
    cudaGetSymbolAddress(&pp, g_P);
    cudaMemsetAsync(aggp, 0, (size_t)NN * DM * sizeof(float));
    cudaMemsetAsync(histp, 0, NN * sizeof(int));
    cudaMemsetAsync(cntp, 0, NN * sizeof(int));

    prep_kernel<<<(25600 + 255) / 256, 256>>>(We1, We2, Wn1, Wn2);
    hist_kernel<<<NE / 256, 256>>>(ei);
    scan_kernel<<<1, 1024>>>();
    permute_kernel<<<NE / 256, 256>>>(ei);
    p_kernel<<<dim3((NN + 127) / 128, 2), 256, P_SMEM_BYTES>>>(nf, (float*)pp);

    edge_kernel<<<NE / 128, 256, E_SMEM_BYTES>>>(nf, ei, ef, (const float*)pp,
                                                 be1, be2, Wi, bi, (float*)aggp);
    node_kernel<<<(NN + 127) / 128, 256, N_SMEM_BYTES>>>(nf, (const float*)aggp,
                                                         bn1, bn2, out);

    idx_to_float_kernel<<<((2 * NE / 4) + 255) / 256, 256>>>(
        (const int4*)ei, (float4*)(out + (size_t)NN * D));
    cudaMemcpyAsync(out + (size_t)NN * D + 2ull * NE, d_in[2],
                    (size_t)NE * DE * sizeof(float), cudaMemcpyDeviceToDevice);
}